// round 1
// baseline (speedup 1.0000x reference)
#include <cuda_runtime.h>

#define T_LEN 2048
#define C_ 8
#define M_ 100
#define N_ 16
#define KCH 4            // m-rows per main thread
#define NMAIN 200        // 8 cells * 25 chunks
#define NTHREADS 256

__global__ __launch_bounds__(NTHREADS, 1)
void kaarma_kernel(const float* __restrict__ x, const float* __restrict__ S,
                   const float* __restrict__ U, const float* __restrict__ A,
                   const float* __restrict__ W1, const float* __restrict__ b1,
                   const float* __restrict__ W2, const float* __restrict__ b2,
                   float* __restrict__ out)
{
    const int tid = threadIdx.x;
    const int b0  = blockIdx.x * 2;
    const int b1i = b0 + 1;

    __shared__ __align__(16) float part[2][C_][25][N_];   // per-thread partial einsum sums
    __shared__ float part2[2][C_][N_];                    // gated per-cell states
    __shared__ float state_sh[2][N_];
    __shared__ float gate_sh[2][C_];
    __shared__ float W1_sh[16], b1_sh[16], W2_sh[16][C_], b2_sh[C_];

    if (tid < 32)  state_sh[tid >> 4][tid & 15] = 0.f;
    if (tid < 16)  { W1_sh[tid] = W1[tid]; b1_sh[tid] = b1[tid]; }
    if (tid < 128) W2_sh[tid >> 3][tid & 7] = W2[tid];
    if (tid < 8)   b2_sh[tid] = b2[tid];

    // Register-resident dictionary slices: S[4][16], A[4][16], U[4], R[4]
    float S_reg[KCH][N_], A_reg[KCH][N_], U_reg[KCH], R_reg[KCH];
    int c = 0, k = 0;
    if (tid < NMAIN) {
        c = tid / 25; k = tid % 25;
        const int m0 = k * KCH;
        #pragma unroll
        for (int i = 0; i < KCH; i++) {
            const int base = (c * M_ + m0 + i) * N_;
            float r = 0.f;
            #pragma unroll
            for (int n = 0; n < N_; n++) {
                float sv = S[base + n];
                S_reg[i][n] = sv;
                A_reg[i][n] = A[base + n];
                r = fmaf(sv, sv, r);
            }
            float uv = U[c * M_ + m0 + i];
            U_reg[i] = uv;
            R_reg[i] = fmaf(uv, uv, r);   // ||S_cm||^2 + U_cm^2
        }
    }
    __syncthreads();

    const float* xrow0 = x + (size_t)b0  * T_LEN;
    const float* xrow1 = x + (size_t)b1i * T_LEN;

    for (int t = 0; t < T_LEN; t++) {
        const float x0 = __ldg(xrow0 + t);
        const float x1 = __ldg(xrow1 + t);

        float st0[N_], st1[N_];
        #pragma unroll
        for (int n = 0; n < N_; n++) { st0[n] = state_sh[0][n]; st1[n] = state_sh[1][n]; }

        if (tid < NMAIN) {
            // q = ||s||^2 + x^2
            float q0 = x0 * x0, q1 = x1 * x1;
            #pragma unroll
            for (int n = 0; n < N_; n++) {
                q0 = fmaf(st0[n], st0[n], q0);
                q1 = fmaf(st1[n], st1[n], q1);
            }
            float acc0[N_], acc1[N_];
            #pragma unroll
            for (int n = 0; n < N_; n++) { acc0[n] = 0.f; acc1[n] = 0.f; }

            #pragma unroll
            for (int i = 0; i < KCH; i++) {
                float d0 = 0.f, d1 = 0.f;
                #pragma unroll
                for (int n = 0; n < N_; n++) {
                    d0 = fmaf(st0[n], S_reg[i][n], d0);
                    d1 = fmaf(st1[n], S_reg[i][n], d1);
                }
                // arg = 2*(s.S + x*U) - (||S||^2+U^2) - (||s||^2+x^2)  == -(dist + du^2)
                float a0 = fmaf(2.f, fmaf(x0, U_reg[i], d0), -R_reg[i] - q0);
                float a1 = fmaf(2.f, fmaf(x1, U_reg[i], d1), -R_reg[i] - q1);
                float p0 = __expf(a0);
                float p1 = __expf(a1);
                #pragma unroll
                for (int n = 0; n < N_; n++) {
                    acc0[n] = fmaf(p0, A_reg[i][n], acc0[n]);
                    acc1[n] = fmaf(p1, A_reg[i][n], acc1[n]);
                }
            }
            float4* pw0 = (float4*)&part[0][c][k][0];
            float4* pw1 = (float4*)&part[1][c][k][0];
            #pragma unroll
            for (int j = 0; j < 4; j++) {
                pw0[j] = make_float4(acc0[4*j], acc0[4*j+1], acc0[4*j+2], acc0[4*j+3]);
                pw1[j] = make_float4(acc1[4*j], acc1[4*j+1], acc1[4*j+2], acc1[4*j+3]);
            }
        } else if (tid == 224 || tid == 225) {
            // gate MLP (depends only on x_t) on warp 7, overlapped with main phase
            const int b = tid - 224;
            const float xb = b ? x1 : x0;
            float h[16];
            #pragma unroll
            for (int j = 0; j < 16; j++) h[j] = fmaxf(0.f, fmaf(xb, W1_sh[j], b1_sh[j]));
            float lg[C_];
            #pragma unroll
            for (int cc = 0; cc < C_; cc++) {
                float s = b2_sh[cc];
                #pragma unroll
                for (int j = 0; j < 16; j++) s = fmaf(h[j], W2_sh[j][cc], s);
                lg[cc] = s;
            }
            float mx = lg[0];
            #pragma unroll
            for (int cc = 1; cc < C_; cc++) mx = fmaxf(mx, lg[cc]);
            float e[C_], se = 0.f;
            #pragma unroll
            for (int cc = 0; cc < C_; cc++) { e[cc] = __expf(lg[cc] - mx); se += e[cc]; }
            const float inv = 1.f / se;
            #pragma unroll
            for (int cc = 0; cc < C_; cc++) gate_sh[b][cc] = e[cc] * inv;
        }
        __syncthreads();

        // Stage B: reduce 25 m-chunk partials per (c,n), apply gate
        if (tid < 128) {
            const int cc = tid >> 4, n = tid & 15;
            #pragma unroll
            for (int b = 0; b < 2; b++) {
                float s = 0.f;
                #pragma unroll
                for (int kk = 0; kk < 25; kk++) s += part[b][cc][kk][n];
                part2[b][cc][n] = gate_sh[b][cc] * s;
            }
        }
        __syncthreads();

        // Stage C: sum over cells -> new state; emit output element
        if (tid < 32) {
            const int b = tid >> 4, n = tid & 15;
            float s = 0.f;
            #pragma unroll
            for (int cc = 0; cc < C_; cc++) s += part2[b][cc][n];
            state_sh[b][n] = s;
            if (n == N_ - 1) out[(size_t)(b ? b1i : b0) * T_LEN + t] = s;
        }
        __syncthreads();
    }
}

extern "C" void kernel_launch(void* const* d_in, const int* in_sizes, int n_in,
                              void* d_out, int out_size) {
    const float* x  = (const float*)d_in[0];
    const float* S  = (const float*)d_in[1];
    const float* U  = (const float*)d_in[2];
    const float* A  = (const float*)d_in[3];
    const float* W1 = (const float*)d_in[4];
    const float* b1 = (const float*)d_in[5];
    const float* W2 = (const float*)d_in[6];
    const float* b2 = (const float*)d_in[7];
    const int B = in_sizes[0] / T_LEN;   // 512
    kaarma_kernel<<<B / 2, NTHREADS>>>(x, S, U, A, W1, b1, W2, b2, (float*)d_out);
}

// round 2
// speedup vs baseline: 1.3064x; 1.3064x over previous
#include <cuda_runtime.h>

#define T_LEN 2048
#define C_ 8
#define M_ 100
#define N_ 16
#define KCH 4
#define NMAIN 200
#define NTHREADS 256
#define KSTRIDE 20             // floats per (c,k) partial row (16 used + 4 pad -> bank spread)
#define CSTRIDE (25*KSTRIDE)   // 500
#define BSTRIDE (C_*CSTRIDE)   // 4000
#define L2E 1.4426950408889634f

__device__ float g_gate[(size_t)T_LEN * 512 * C_];   // [t][b][c]

// ---------- packed f32x2 helpers ----------
__device__ __forceinline__ unsigned long long ffma2(unsigned long long a, unsigned long long b,
                                                    unsigned long long c) {
    unsigned long long d;
    asm("fma.rn.f32x2 %0, %1, %2, %3;" : "=l"(d) : "l"(a), "l"(b), "l"(c));
    return d;
}
__device__ __forceinline__ unsigned long long pack2(float lo, float hi) {
    unsigned long long d; asm("mov.b64 %0, {%1, %2};" : "=l"(d) : "f"(lo), "f"(hi)); return d;
}
__device__ __forceinline__ void unpack2(unsigned long long v, float& lo, float& hi) {
    asm("mov.b64 {%0, %1}, %2;" : "=f"(lo), "=f"(hi) : "l"(v));
}
__device__ __forceinline__ float ex2f(float a) {
    float r; asm("ex2.approx.f32 %0, %1;" : "=f"(r) : "f"(a)); return r;
}

// ---------- gate pre-pass: gate[t][b][c] for all (t,b) ----------
__global__ void gate_kernel(const float* __restrict__ x,
                            const float* __restrict__ W1, const float* __restrict__ b1,
                            const float* __restrict__ W2, const float* __restrict__ b2,
                            int B) {
    int idx = blockIdx.x * blockDim.x + threadIdx.x;   // idx = t*B + b
    if (idx >= B * T_LEN) return;
    int t = idx / B, b = idx - t * B;
    float xv = __ldg(&x[(size_t)b * T_LEN + t]);
    float lg[C_];
    #pragma unroll
    for (int c = 0; c < C_; c++) lg[c] = __ldg(&b2[c]);
    #pragma unroll
    for (int j = 0; j < 16; j++) {
        float h = fmaxf(0.f, fmaf(xv, __ldg(&W1[j]), __ldg(&b1[j])));
        #pragma unroll
        for (int c = 0; c < C_; c++) lg[c] = fmaf(h, __ldg(&W2[j * C_ + c]), lg[c]);
    }
    float mx = lg[0];
    #pragma unroll
    for (int c = 1; c < C_; c++) mx = fmaxf(mx, lg[c]);
    float e[C_], se = 0.f;
    #pragma unroll
    for (int c = 0; c < C_; c++) { e[c] = __expf(lg[c] - mx); se += e[c]; }
    float inv = 1.f / se;
    float* dst = &g_gate[(size_t)idx * C_];
    #pragma unroll
    for (int c = 0; c < C_; c++) dst[c] = e[c] * inv;
}

// ---------- main recurrence ----------
__global__ __launch_bounds__(NTHREADS, 1)
void kaarma_kernel(const float* __restrict__ x, const float* __restrict__ S,
                   const float* __restrict__ U, const float* __restrict__ A,
                   float* __restrict__ out, int B) {
    const int tid = threadIdx.x;
    const int b0  = blockIdx.x * 2;

    __shared__ __align__(16) float part[2 * BSTRIDE];     // 32 KB partials
    __shared__ __align__(16) float state_sh[2][N_];
    __shared__ float gate_sh[2][16];                      // double-buffered [b*8+c]
    __shared__ float f_sh[2];                             // exp(-||s||^2 - x^2) per batch

    if (tid < 32) state_sh[tid >> 4][tid & 15] = 0.f;

    // register-resident dictionary, pre-scaled into log2 domain
    unsigned long long S2[KCH][8], A2[KCH][8];
    float U2l[KCH], Rn[KCH];
    int c = 0, k = 0;
    if (tid < NMAIN) {
        c = tid / 25; k = tid % 25;
        const int m0 = k * KCH;
        #pragma unroll
        for (int i = 0; i < KCH; i++) {
            const int base = (c * M_ + m0 + i) * N_;
            float r = 0.f, sv[N_];
            #pragma unroll
            for (int n = 0; n < N_; n++) { sv[n] = S[base + n]; r = fmaf(sv[n], sv[n], r); }
            float uv = U[c * M_ + m0 + i];
            Rn[i]  = -L2E * fmaf(uv, uv, r);     // -log2e*(||S||^2+U^2)
            U2l[i] = 2.f * L2E * uv;
            #pragma unroll
            for (int j = 0; j < 8; j++) {
                S2[i][j] = pack2(2.f * L2E * sv[2 * j], 2.f * L2E * sv[2 * j + 1]);
                A2[i][j] = pack2(A[base + 2 * j], A[base + 2 * j + 1]);
            }
        }
    }
    // preload gates for t=0
    if (tid >= 240) gate_sh[0][tid - 240] = __ldg(&g_gate[((size_t)0 * B + b0) * C_ + (tid - 240)]);
    __syncthreads();

    const float* xrow0 = x + (size_t)b0 * T_LEN;
    const float* xrow1 = xrow0 + T_LEN;

    for (int t = 0; t < T_LEN; t++) {
        const float x0 = __ldg(xrow0 + t);
        const float x1 = __ldg(xrow1 + t);

        if (tid < NMAIN) {
            // load state packed (f32x2 over n-pairs)
            unsigned long long st0[8], st1[8];
            const unsigned long long* sp0 = (const unsigned long long*)state_sh[0];
            const unsigned long long* sp1 = (const unsigned long long*)state_sh[1];
            #pragma unroll
            for (int j = 0; j < 8; j++) { st0[j] = sp0[j]; st1[j] = sp1[j]; }

            unsigned long long acc0[8], acc1[8];
            #pragma unroll
            for (int j = 0; j < 8; j++) { acc0[j] = 0ull; acc1[j] = 0ull; }

            #pragma unroll
            for (int i = 0; i < KCH; i++) {
                unsigned long long d0 = 0ull, d1 = 0ull;
                #pragma unroll
                for (int j = 0; j < 8; j++) {
                    d0 = ffma2(st0[j], S2[i][j], d0);
                    d1 = ffma2(st1[j], S2[i][j], d1);
                }
                float l0, h0, l1, h1;
                unpack2(d0, l0, h0); unpack2(d1, l1, h1);
                float a0 = (l0 + h0) + fmaf(x0, U2l[i], Rn[i]);
                float a1 = (l1 + h1) + fmaf(x1, U2l[i], Rn[i]);
                float p0 = ex2f(a0), p1 = ex2f(a1);
                unsigned long long p0p = pack2(p0, p0), p1p = pack2(p1, p1);
                #pragma unroll
                for (int j = 0; j < 8; j++) {
                    acc0[j] = ffma2(p0p, A2[i][j], acc0[j]);
                    acc1[j] = ffma2(p1p, A2[i][j], acc1[j]);
                }
            }
            float* dst0 = &part[c * CSTRIDE + k * KSTRIDE];
            float* dst1 = dst0 + BSTRIDE;
            #pragma unroll
            for (int j = 0; j < 4; j++) {
                ((ulonglong2*)dst0)[j] = make_ulonglong2(acc0[2 * j], acc0[2 * j + 1]);
                ((ulonglong2*)dst1)[j] = make_ulonglong2(acc1[2 * j], acc1[2 * j + 1]);
            }
        } else if (tid >= 224) {
            const int lane = tid & 31;
            if (lane < 2) {
                // per-batch scalar factor exp(-(||s||^2 + x^2)), overlapped with main phase
                const float xb = lane ? x1 : x0;
                float ss = xb * xb;
                #pragma unroll
                for (int n = 0; n < N_; n++) {
                    float s = state_sh[lane][n];
                    ss = fmaf(s, s, ss);
                }
                f_sh[lane] = __expf(-ss);
            } else if (lane >= 16) {
                // prefetch next timestep's gates (double buffer)
                int tn = (t + 1 < T_LEN) ? t + 1 : t;
                gate_sh[(t + 1) & 1][lane - 16] =
                    __ldg(&g_gate[((size_t)tn * B + b0) * C_ + (lane - 16)]);
            }
        }
        __syncthreads();

        // merged reduction: thread = (b, n, c); sum 25 k-partials, gate, reduce over c
        {
            const int rb = tid >> 7, rn = (tid >> 3) & 15, rc = tid & 7;
            const float* p = &part[rb * BSTRIDE + rc * CSTRIDE + rn];
            float v = 0.f;
            #pragma unroll
            for (int kk = 0; kk < 25; kk++) v += p[kk * KSTRIDE];
            v *= gate_sh[t & 1][rb * 8 + rc];
            #pragma unroll
            for (int o = 1; o < 8; o <<= 1) v += __shfl_xor_sync(0xffffffffu, v, o);
            if (rc == 0) {
                float nv = v * f_sh[rb];
                state_sh[rb][rn] = nv;
                if (rn == N_ - 1) out[(size_t)(b0 + rb) * T_LEN + t] = nv;
            }
        }
        __syncthreads();
    }
}

extern "C" void kernel_launch(void* const* d_in, const int* in_sizes, int n_in,
                              void* d_out, int out_size) {
    const float* x  = (const float*)d_in[0];
    const float* S  = (const float*)d_in[1];
    const float* U  = (const float*)d_in[2];
    const float* A  = (const float*)d_in[3];
    const float* W1 = (const float*)d_in[4];
    const float* b1 = (const float*)d_in[5];
    const float* W2 = (const float*)d_in[6];
    const float* b2 = (const float*)d_in[7];
    const int B = in_sizes[0] / T_LEN;   // 512

    gate_kernel<<<(B * T_LEN + 255) / 256, 256>>>(x, W1, b1, W2, b2, B);
    kaarma_kernel<<<B / 2, NTHREADS>>>(x, S, U, A, (float*)d_out, B);
}

// round 3
// speedup vs baseline: 1.3447x; 1.0293x over previous
#include <cuda_runtime.h>

#define T_LEN 2048
#define C_ 8
#define M_ 100
#define N_ 16
#define KCH 4
#define NMAIN 200
#define NTHREADS 256
#define KSTRIDE 20                 // floats per (c,k) partial row (16 + 4 pad -> conflict-free)
#define CSTRIDE (25*KSTRIDE)       // 500
#define BSTRIDE (C_*CSTRIDE)       // 4000 floats per batch slot
#define SMEM_FLOATS (4*BSTRIDE + 64 + 64 + 8)
#define L2E 1.4426950408889634f

__device__ float g_gate[(size_t)T_LEN * 512 * C_];   // [t][b][c]

typedef unsigned long long u64;

__device__ __forceinline__ u64 ffma2(u64 a, u64 b, u64 c) {
    u64 d; asm("fma.rn.f32x2 %0, %1, %2, %3;" : "=l"(d) : "l"(a), "l"(b), "l"(c)); return d;
}
__device__ __forceinline__ u64 pack2(float lo, float hi) {
    u64 d; asm("mov.b64 %0, {%1, %2};" : "=l"(d) : "f"(lo), "f"(hi)); return d;
}
__device__ __forceinline__ void unpack2(u64 v, float& lo, float& hi) {
    asm("mov.b64 {%0, %1}, %2;" : "=f"(lo), "=f"(hi) : "l"(v));
}
__device__ __forceinline__ float ex2f(float a) {
    float r; asm("ex2.approx.f32 %0, %1;" : "=f"(r) : "f"(a)); return r;
}

// ---------- gate pre-pass ----------
__global__ void gate_kernel(const float* __restrict__ x,
                            const float* __restrict__ W1, const float* __restrict__ b1,
                            const float* __restrict__ W2, const float* __restrict__ b2,
                            int B) {
    int idx = blockIdx.x * blockDim.x + threadIdx.x;   // t*B + b
    if (idx >= B * T_LEN) return;
    int t = idx / B, b = idx - t * B;
    float xv = __ldg(&x[(size_t)b * T_LEN + t]);
    float lg[C_];
    #pragma unroll
    for (int c = 0; c < C_; c++) lg[c] = __ldg(&b2[c]);
    #pragma unroll
    for (int j = 0; j < 16; j++) {
        float h = fmaxf(0.f, fmaf(xv, __ldg(&W1[j]), __ldg(&b1[j])));
        #pragma unroll
        for (int c = 0; c < C_; c++) lg[c] = fmaf(h, __ldg(&W2[j * C_ + c]), lg[c]);
    }
    float mx = lg[0];
    #pragma unroll
    for (int c = 1; c < C_; c++) mx = fmaxf(mx, lg[c]);
    float e[C_], se = 0.f;
    #pragma unroll
    for (int c = 0; c < C_; c++) { e[c] = __expf(lg[c] - mx); se += e[c]; }
    float inv = 1.f / se;
    float* dst = &g_gate[(size_t)idx * C_];
    #pragma unroll
    for (int c = 0; c < C_; c++) dst[c] = e[c] * inv;
}

// ---------- main recurrence: 4 batches per block, single wave ----------
__global__ __launch_bounds__(NTHREADS, 1)
void kaarma_kernel(const float* __restrict__ x, const float* __restrict__ S,
                   const float* __restrict__ U, const float* __restrict__ A,
                   float* __restrict__ out, int B) {
    extern __shared__ __align__(16) float sm[];
    float* part     = sm;                      // [4][BSTRIDE]
    float* state_sh = sm + 4 * BSTRIDE;        // [4][16]
    float* gate_sh  = state_sh + 64;           // [2][32] double-buffered
    float* f_sh     = gate_sh + 64;            // [4]

    const int tid = threadIdx.x;
    const int b0  = blockIdx.x * 4;

    if (tid < 64) state_sh[tid] = 0.f;

    // register-resident dictionary (log2-domain prescale)
    u64 S2[KCH][8], A2[KCH][8];
    float U2l[KCH], Rn[KCH];
    int c = 0, k = 0;
    if (tid < NMAIN) {
        c = tid / 25; k = tid % 25;
        const int m0 = k * KCH;
        #pragma unroll
        for (int i = 0; i < KCH; i++) {
            const int base = (c * M_ + m0 + i) * N_;
            float r = 0.f, sv[N_];
            #pragma unroll
            for (int n = 0; n < N_; n++) { sv[n] = S[base + n]; r = fmaf(sv[n], sv[n], r); }
            float uv = U[c * M_ + m0 + i];
            Rn[i]  = -L2E * fmaf(uv, uv, r);
            U2l[i] = 2.f * L2E * uv;
            #pragma unroll
            for (int j = 0; j < 8; j++) {
                S2[i][j] = pack2(2.f * L2E * sv[2 * j], 2.f * L2E * sv[2 * j + 1]);
                A2[i][j] = pack2(A[base + 2 * j], A[base + 2 * j + 1]);
            }
        }
    }
    // preload gates for t=0 (one coalesced 128B load)
    if (tid >= 224) gate_sh[tid - 224] = __ldg(&g_gate[((size_t)0 * B + b0) * C_ + (tid - 224)]);
    __syncthreads();

    const float* xrow = x + (size_t)b0 * T_LEN;

    for (int t = 0; t < T_LEN; t++) {
        if (tid < NMAIN) {
            float xv[4];
            #pragma unroll
            for (int b = 0; b < 4; b++) xv[b] = __ldg(xrow + (size_t)b * T_LEN + t);

            for (int p = 0; p < 2; p++) {          // pass over batch pairs {0,1},{2,3}
                const float xa = xv[2 * p], xb = xv[2 * p + 1];
                const u64* sp0 = (const u64*)(state_sh + (2 * p) * 16);
                const u64* sp1 = (const u64*)(state_sh + (2 * p + 1) * 16);
                u64 st0[8], st1[8], acc0[8], acc1[8];
                #pragma unroll
                for (int j = 0; j < 8; j++) {
                    st0[j] = sp0[j]; st1[j] = sp1[j];
                    acc0[j] = 0ull;  acc1[j] = 0ull;
                }
                #pragma unroll
                for (int i = 0; i < KCH; i++) {
                    u64 d0 = 0ull, d1 = 0ull;
                    #pragma unroll
                    for (int j = 0; j < 8; j++) {
                        d0 = ffma2(st0[j], S2[i][j], d0);
                        d1 = ffma2(st1[j], S2[i][j], d1);
                    }
                    float l0, h0, l1, h1;
                    unpack2(d0, l0, h0); unpack2(d1, l1, h1);
                    float a0 = (l0 + h0) + fmaf(xa, U2l[i], Rn[i]);
                    float a1 = (l1 + h1) + fmaf(xb, U2l[i], Rn[i]);
                    float p0 = ex2f(a0), p1 = ex2f(a1);
                    u64 p0p = pack2(p0, p0), p1p = pack2(p1, p1);
                    #pragma unroll
                    for (int j = 0; j < 8; j++) {
                        acc0[j] = ffma2(p0p, A2[i][j], acc0[j]);
                        acc1[j] = ffma2(p1p, A2[i][j], acc1[j]);
                    }
                }
                float* dst0 = part + (2 * p) * BSTRIDE + c * CSTRIDE + k * KSTRIDE;
                float* dst1 = dst0 + BSTRIDE;
                #pragma unroll
                for (int j = 0; j < 4; j++) {
                    ((ulonglong2*)dst0)[j] = make_ulonglong2(acc0[2 * j], acc0[2 * j + 1]);
                    ((ulonglong2*)dst1)[j] = make_ulonglong2(acc1[2 * j], acc1[2 * j + 1]);
                }
            }
        } else if (tid < 224) {
            const int i = tid - 200;
            if (i < 4) {
                // per-batch factor exp(-(||s||^2 + x^2)), overlapped with main phase
                float xb = __ldg(xrow + (size_t)i * T_LEN + t);
                float ss = xb * xb;
                #pragma unroll
                for (int n = 0; n < N_; n++) {
                    float s = state_sh[i * 16 + n];
                    ss = fmaf(s, s, ss);
                }
                f_sh[i] = __expf(-ss);
            }
        } else {
            // warp 7: prefetch next timestep's 32 gates (coalesced, double-buffered)
            const int lane = tid - 224;
            int tn = (t + 1 < T_LEN) ? t + 1 : t;
            gate_sh[((t + 1) & 1) * 32 + lane] =
                __ldg(&g_gate[((size_t)tn * B + b0) * C_ + lane]);
        }
        __syncthreads();

        // reduction: thread = (rb, rn, rc); handles batches rb and rb+2
        {
            const int rb = tid >> 7, rn = (tid >> 3) & 15, rc = tid & 7;
            const float* pA = part + rb * BSTRIDE + rc * CSTRIDE + rn;
            const float* pB = pA + 2 * BSTRIDE;
            float v0 = 0.f, v1 = 0.f;
            #pragma unroll
            for (int kk = 0; kk < 25; kk++) {
                v0 += pA[kk * KSTRIDE];
                v1 += pB[kk * KSTRIDE];
            }
            const float* gb = gate_sh + (t & 1) * 32;
            v0 *= gb[rb * 8 + rc];
            v1 *= gb[(rb + 2) * 8 + rc];
            #pragma unroll
            for (int o = 1; o < 8; o <<= 1) {
                v0 += __shfl_xor_sync(0xffffffffu, v0, o);
                v1 += __shfl_xor_sync(0xffffffffu, v1, o);
            }
            if (rc == 0) {
                float nv0 = v0 * f_sh[rb];
                float nv1 = v1 * f_sh[rb + 2];
                state_sh[rb * 16 + rn] = nv0;
                state_sh[(rb + 2) * 16 + rn] = nv1;
                if (rn == N_ - 1) {
                    out[(size_t)(b0 + rb) * T_LEN + t] = nv0;
                    out[(size_t)(b0 + rb + 2) * T_LEN + t] = nv1;
                }
            }
        }
        __syncthreads();
    }
}

extern "C" void kernel_launch(void* const* d_in, const int* in_sizes, int n_in,
                              void* d_out, int out_size) {
    const float* x  = (const float*)d_in[0];
    const float* S  = (const float*)d_in[1];
    const float* U  = (const float*)d_in[2];
    const float* A  = (const float*)d_in[3];
    const float* W1 = (const float*)d_in[4];
    const float* b1 = (const float*)d_in[5];
    const float* W2 = (const float*)d_in[6];
    const float* b2 = (const float*)d_in[7];
    const int B = in_sizes[0] / T_LEN;   // 512

    static int smem_set = 0;
    if (!smem_set) {
        cudaFuncSetAttribute(kaarma_kernel,
                             cudaFuncAttributeMaxDynamicSharedMemorySize,
                             SMEM_FLOATS * sizeof(float));
        smem_set = 1;
    }
    gate_kernel<<<(B * T_LEN + 255) / 256, 256>>>(x, W1, b1, W2, b2, B);
    kaarma_kernel<<<B / 4, NTHREADS, SMEM_FLOATS * sizeof(float)>>>(
        x, S, U, A, (float*)d_out, B);
}